// round 1
// baseline (speedup 1.0000x reference)
#include <cuda_runtime.h>
#include <cstdint>
#include <cstddef>

// ---------------------------------------------------------------------------
// Lfm2ShortConv: out = ((C ⊙ causal_depthwise_conv3(B ⊙ x)) ) @ W_out^T
// where [B|C|x] = hidden @ W_in^T.
// Shapes: hidden [2,4096,2048] fp32, W_in [6144,2048], conv_w [2048,1,3],
// W_out [2048,2048]. All GEMMs are TN (both operands K-major, K=2048).
// Strategy: TF32 mma.sync GEMMs (fp32 accum) + tiny fused conv/gate kernel.
// ---------------------------------------------------------------------------

#define M_TOTAL 8192
#define K_DIM   2048
#define N1      6144
#define N2      2048
#define SEQ     4096
#define HD      2048

// Scratch (allocation-free rule: __device__ globals)
__device__ float g_BCx[(size_t)M_TOTAL * N1];   // 201 MB
__device__ float g_y  [(size_t)M_TOTAL * N2];   // 67 MB

// ---- GEMM tiling ----------------------------------------------------------
constexpr int BM = 128, BN = 128, BK = 32;
constexpr int NTHREADS = 256;                 // 8 warps: 2 (M) x 4 (N)
constexpr int WM_ = 64, WN_ = 32;             // warp tile
constexpr int MT = WM_ / 16;                  // 4 m16 tiles
constexpr int NT = WN_ / 8;                   // 4 n8 tiles
constexpr int ASTRIDE = BK + 4;               // pad to kill bank conflicts
constexpr int SMEM_FLOATS = 2 * BM * ASTRIDE + 2 * BN * ASTRIDE;
constexpr int SMEM_BYTES  = SMEM_FLOATS * 4;  // 73728

// ---- PTX helpers ----------------------------------------------------------
__device__ __forceinline__ void cp_async16(void* smem_dst, const void* gsrc) {
    uint32_t saddr = (uint32_t)__cvta_generic_to_shared(smem_dst);
    asm volatile("cp.async.cg.shared.global [%0], [%1], 16;\n"
                 :: "r"(saddr), "l"(gsrc));
}
__device__ __forceinline__ void cp_commit() {
    asm volatile("cp.async.commit_group;\n");
}
template <int N>
__device__ __forceinline__ void cp_wait() {
    asm volatile("cp.async.wait_group %0;\n" :: "n"(N));
}
__device__ __forceinline__ uint32_t f2tf(float f) {
    uint32_t u;
    asm("cvt.rna.tf32.f32 %0, %1;" : "=r"(u) : "f"(f));
    return u;
}
__device__ __forceinline__ void mma_tf32(float* c, const uint32_t* a, const uint32_t* b) {
    asm volatile(
        "mma.sync.aligned.m16n8k8.row.col.f32.tf32.tf32.f32 "
        "{%0,%1,%2,%3}, {%4,%5,%6,%7}, {%8,%9}, {%0,%1,%2,%3};\n"
        : "+f"(c[0]), "+f"(c[1]), "+f"(c[2]), "+f"(c[3])
        : "r"(a[0]), "r"(a[1]), "r"(a[2]), "r"(a[3]), "r"(b[0]), "r"(b[1]));
}

// ---- TN GEMM: C[M,N] = A[M,K] * B[N,K]^T  (fp32 in/out, tf32 compute) -----
__global__ void __launch_bounds__(NTHREADS)
gemm_tf32_tn(const float* __restrict__ A, const float* __restrict__ B,
             float* __restrict__ C, int N, int K)
{
    extern __shared__ float sm[];
    float* As = sm;                       // [2][BM][ASTRIDE]
    float* Bs = sm + 2 * BM * ASTRIDE;    // [2][BN][ASTRIDE]

    const int tid  = threadIdx.x;
    const int lane = tid & 31;
    const int warp = tid >> 5;
    const int wm = (warp >> 2) * WM_;     // 0 or 64
    const int wn = (warp & 3)  * WN_;     // 0,32,64,96
    const int g  = lane >> 2;             // groupID
    const int c  = lane & 3;              // threadID_in_group

    const int brow = blockIdx.y * BM;
    const int bcol = blockIdx.x * BN;
    const float* Ag = A + (size_t)brow * K;
    const float* Bg = B + (size_t)bcol * K;

    float acc[MT][NT][4];
    #pragma unroll
    for (int i = 0; i < MT; i++)
        #pragma unroll
        for (int j = 0; j < NT; j++)
            #pragma unroll
            for (int q = 0; q < 4; q++) acc[i][j][q] = 0.f;

    const int KT = K / BK;

    auto prefetch = [&](int kt, int st) {
        const int k0 = kt * BK;
        #pragma unroll
        for (int i = 0; i < 4; i++) {                     // A tile: 128x32
            int idx = tid + i * NTHREADS;                 // 0..1023 chunks
            int r  = idx >> 3;                            // 8 x 16B per row
            int cc = (idx & 7) << 2;
            cp_async16(&As[st * BM * ASTRIDE + r * ASTRIDE + cc],
                       Ag + (size_t)r * K + k0 + cc);
        }
        #pragma unroll
        for (int i = 0; i < 4; i++) {                     // B tile: 128x32
            int idx = tid + i * NTHREADS;
            int r  = idx >> 3;
            int cc = (idx & 7) << 2;
            cp_async16(&Bs[st * BN * ASTRIDE + r * ASTRIDE + cc],
                       Bg + (size_t)r * K + k0 + cc);
        }
        cp_commit();
    };

    prefetch(0, 0);

    for (int kt = 0; kt < KT; ++kt) {
        const int st = kt & 1;
        cp_wait<0>();
        __syncthreads();
        if (kt + 1 < KT) prefetch(kt + 1, st ^ 1);

        const float* as = &As[st * BM * ASTRIDE];
        const float* bs = &Bs[st * BN * ASTRIDE];

        #pragma unroll
        for (int ks = 0; ks < BK / 8; ++ks) {
            uint32_t af[MT][4], bf[NT][2];
            #pragma unroll
            for (int mi = 0; mi < MT; ++mi) {
                const int r0 = wm + mi * 16 + g;
                const float* p  = as + r0 * ASTRIDE + ks * 8 + c;
                const float* p8 = p + 8 * ASTRIDE;
                // m16n8k8.tf32 A frag: a0=(g,c) a1=(g+8,c) a2=(g,c+4) a3=(g+8,c+4)
                af[mi][0] = f2tf(p[0]);
                af[mi][1] = f2tf(p8[0]);
                af[mi][2] = f2tf(p[4]);
                af[mi][3] = f2tf(p8[4]);
            }
            #pragma unroll
            for (int ni = 0; ni < NT; ++ni) {
                const int n0 = wn + ni * 8 + g;
                const float* p = bs + n0 * ASTRIDE + ks * 8 + c;
                // B frag: b0=(k=c, n=g), b1=(k=c+4, n=g)
                bf[ni][0] = f2tf(p[0]);
                bf[ni][1] = f2tf(p[4]);
            }
            #pragma unroll
            for (int mi = 0; mi < MT; ++mi)
                #pragma unroll
                for (int ni = 0; ni < NT; ++ni)
                    mma_tf32(acc[mi][ni], af[mi], bf[ni]);
        }
        __syncthreads();
    }

    // Epilogue: C frag c0=(g,2c) c1=(g,2c+1) c2=(g+8,2c) c3=(g+8,2c+1)
    #pragma unroll
    for (int mi = 0; mi < MT; ++mi) {
        const int r0 = brow + wm + mi * 16 + g;
        #pragma unroll
        for (int ni = 0; ni < NT; ++ni) {
            const int cc = bcol + wn + ni * 8 + 2 * c;
            *reinterpret_cast<float2*>(C + (size_t)r0 * N + cc) =
                make_float2(acc[mi][ni][0], acc[mi][ni][1]);
            *reinterpret_cast<float2*>(C + (size_t)(r0 + 8) * N + cc) =
                make_float2(acc[mi][ni][2], acc[mi][ni][3]);
        }
    }
}

// ---- Conv + gating: y[m,h] = C[m,h] * sum_k w[h,k]*Bx[m-2+k, h] -----------
// BCx layout per row m: [B(0:2048) | C(2048:4096) | x(4096:6144)]
__global__ void __launch_bounds__(256)
conv_gate_kernel(const float* __restrict__ BCx, const float* __restrict__ w,
                 float* __restrict__ y)
{
    const int idx = blockIdx.x * blockDim.x + threadIdx.x;  // < 8192*2048
    const int h = idx & (HD - 1);
    const int m = idx >> 11;
    const int s = m & (SEQ - 1);

    const float* row = BCx + (size_t)m * N1;
    const float w0 = w[h * 3 + 0];
    const float w1 = w[h * 3 + 1];
    const float w2 = w[h * 3 + 2];

    float acc = w2 * (row[h] * row[2 * HD + h]);
    if (s >= 1) {
        const float* r1 = row - N1;
        acc += w1 * (r1[h] * r1[2 * HD + h]);
    }
    if (s >= 2) {
        const float* r2 = row - 2 * N1;
        acc += w0 * (r2[h] * r2[2 * HD + h]);
    }
    y[idx] = acc * row[HD + h];
}

// ---------------------------------------------------------------------------
extern "C" void kernel_launch(void* const* d_in, const int* in_sizes, int n_in,
                              void* d_out, int out_size)
{
    const float* hs    = (const float*)d_in[0];   // [2,4096,2048]
    const float* Win   = (const float*)d_in[1];   // [6144,2048]
    const float* convw = (const float*)d_in[2];   // [2048,1,3]
    const float* Wout  = (const float*)d_in[3];   // [2048,2048]
    float* out = (float*)d_out;

    float *bcx = nullptr, *y = nullptr;
    cudaGetSymbolAddress((void**)&bcx, g_BCx);
    cudaGetSymbolAddress((void**)&y,   g_y);

    cudaFuncSetAttribute(gemm_tf32_tn,
                         cudaFuncAttributeMaxDynamicSharedMemorySize, SMEM_BYTES);

    // GEMM1: BCx = hidden @ W_in^T   [8192 x 6144]
    gemm_tf32_tn<<<dim3(N1 / BN, M_TOTAL / BM), NTHREADS, SMEM_BYTES>>>(
        hs, Win, bcx, N1, K_DIM);

    // conv + gating -> y [8192 x 2048]
    conv_gate_kernel<<<(M_TOTAL * HD) / 256, 256>>>(bcx, convw, y);

    // GEMM2: out = y @ W_out^T   [8192 x 2048]
    gemm_tf32_tn<<<dim3(N2 / BN, M_TOTAL / BM), NTHREADS, SMEM_BYTES>>>(
        y, Wout, out, N2, K_DIM);
}